// round 4
// baseline (speedup 1.0000x reference)
#include <cuda_runtime.h>

// SparseVolumeReconstructionLinear — GB300 sm_103a
// Fixed constants (SIZE=161, MARGIN=3, BATCH=256, INPUT_SIZE=8):
#define BATCH   256
#define ISIZE   8
#define HW      80              // SIZE // 2
#define PX      81              // SIZE//2 + 1   (x extent of 2D half-grid)
#define PTS     (161 * 81)      // 13041 points
#define BZM     167             // SIZE + 2*MARGIN
#define BZ2     83              // BZM // 2
#define GX      84              // BZM//2 + 1    (x extent of 3D half-grid)
#define GZSTRIDE (BZM * GX)     // 14028
#define GRID_ELEMS (BZM * BZM * GX)  // 2,342,844
#define MR2     6400

__device__ int g_is64;   // 1 if grid3d_index is int64 on device, else 0

// Probe (z=83,y=83): int32 word r+1 is an interior ball index (large positive)
// if the buffer is int32, or the high word of a positive int64 (== 0) if int64.
__global__ void detect_kernel(const int* __restrict__ g)
{
    const int r = 83 * GZSTRIDE + 83 * GX;   // even
    g_is64 = (g[r + 1] == 0) ? 1 : 0;
}

__global__ __launch_bounds__(256) void svr_kernel(
    const float*  __restrict__ input,    // (256, 8)
    const float4* __restrict__ weight,   // (Nw, 8, 2) -> Nw*4 float4
    const float2* __restrict__ bias,     // (Nw, 2)
    const int*    __restrict__ grid3d,   // (167,167,84) int32 (or int64 LE)
    const float*  __restrict__ rot,      // (256, 3, 3)
    float2*       __restrict__ out)      // (256, 13041, 2)
{
    const int b = blockIdx.y;
    const int p = blockIdx.x * blockDim.x + threadIdx.x;
    if (p >= PTS) return;

    const int xi2 = p % PX;           // coord.x  (0..80)
    const int iy  = p / PX - HW;      // coord.y  (-80..80)

    const size_t oidx = (size_t)b * PTS + p;

    if (xi2 * xi2 + iy * iy > MR2) {           // exact validity mask
        out[oidx] = make_float2(0.f, 0.f);
        return;
    }

    const int is64 = g_is64;                   // uniform

    const float* R = rot + b * 9;
    const float x = (float)xi2, y = (float)iy;
    float cx = R[0] * x + R[1] * y;
    float cy = R[3] * x + R[4] * y;
    float cz = R[6] * x + R[7] * y;

    float simag = 1.f;
    if (cx < 0.f) { cx = -cx; cy = -cy; cz = -cz; simag = -1.f; }

    const float fx = floorf(cx), fy = floorf(cy), fz = floorf(cz);
    const int   ix = (int)fx,    iyc = (int)fy,   iz = (int)fz;
    const float tx = cx - fx,    ty = cy - fy,    tz = cz - fz;

    const float wxl[2] = {1.f - tx, tx};
    const float wyl[2] = {1.f - ty, ty};
    const float wzl[2] = {1.f - tz, tz};

    const float* inb = input + b * ISIZE;      // uniform per block -> L1 broadcast
    const float i0 = inb[0], i1 = inb[1], i2 = inb[2], i3 = inb[3];
    const float i4 = inb[4], i5 = inb[5], i6 = inb[6], i7 = inb[7];

    float ar = 0.f, ai = 0.f;

    #pragma unroll
    for (int dz = 0; dz < 2; ++dz) {
        const int zbase = (iz + dz + BZ2) * GZSTRIDE;
        #pragma unroll
        for (int dy = 0; dy < 2; ++dy) {
            const int ybase = zbase + (iyc + dy + BZ2) * GX + ix;
            const float wzy = wzl[dz] * wyl[dy];
            #pragma unroll
            for (int dx = 0; dx < 2; ++dx) {
                const int lin = ybase + dx;
                const int j = is64 ? __ldg(grid3d + 2 * lin)   // low word (LE)
                                   : __ldg(grid3d + lin);
                if (j >= 0) {
                    const float4* wp = weight + (size_t)j * 4;
                    const float4 w0 = __ldg(wp + 0);
                    const float4 w1 = __ldg(wp + 1);
                    const float4 w2 = __ldg(wp + 2);
                    const float4 w3 = __ldg(wp + 3);
                    const float2 bb = __ldg(bias + j);
                    float vr = bb.x + i0 * w0.x + i1 * w0.z + i2 * w1.x + i3 * w1.z
                                    + i4 * w2.x + i5 * w2.z + i6 * w3.x + i7 * w3.z;
                    float vi = bb.y + i0 * w0.y + i1 * w0.w + i2 * w1.y + i3 * w1.w
                                    + i4 * w2.y + i5 * w2.w + i6 * w3.y + i7 * w3.w;
                    const float w = wzy * wxl[dx];
                    ar += w * vr;
                    ai += w * vi;
                }
            }
        }
    }

    out[oidx] = make_float2(ar, ai * simag);
}

extern "C" void kernel_launch(void* const* d_in, const int* in_sizes, int n_in,
                              void* d_out, int out_size)
{
    // Identify inputs by element count — robust to metadata ordering.
    const void* p_input  = nullptr;  // 2048
    const void* p_rot    = nullptr;  // 2304
    const void* p_grid   = nullptr;  // 2,342,844
    const void* p_weight = nullptr;  // Nw*16 (larger of remaining pair)
    const void* p_bias   = nullptr;  // Nw*2
    long long wcand[2] = {0, 0};
    const void* pcand[2] = {nullptr, nullptr};
    int ncand = 0;

    for (int i = 0; i < n_in; ++i) {
        const long long s = in_sizes[i];
        if      (s == BATCH * ISIZE)           p_input = d_in[i];
        else if (s == BATCH * 9)               p_rot   = d_in[i];
        else if (s == (long long)GRID_ELEMS)   p_grid  = d_in[i];
        else if (s == PTS * 2 || s == 1)       { /* grid2d_coord / max_r unused */ }
        else if (ncand < 2)                    { wcand[ncand] = s; pcand[ncand] = d_in[i]; ++ncand; }
    }
    if (ncand == 2) {
        if (wcand[0] > wcand[1]) { p_weight = pcand[0]; p_bias = pcand[1]; }
        else                     { p_weight = pcand[1]; p_bias = pcand[0]; }
    }

    detect_kernel<<<1, 1>>>((const int*)p_grid);

    dim3 grid((PTS + 255) / 256, BATCH);
    svr_kernel<<<grid, 256>>>((const float*)p_input,
                              (const float4*)p_weight,
                              (const float2*)p_bias,
                              (const int*)p_grid,
                              (const float*)p_rot,
                              (float2*)d_out);
}

// round 5
// speedup vs baseline: 1.6935x; 1.6935x over previous
#include <cuda_runtime.h>

// SparseVolumeReconstructionLinear — GB300 sm_103a
// Fixed constants (SIZE=161, MARGIN=3, BATCH=256, INPUT_SIZE=8):
#define BATCH   256
#define ISIZE   8
#define HW      80              // SIZE // 2
#define PX      81              // SIZE//2 + 1
#define PTS     (161 * 81)      // 13041 points
#define BZM     167             // SIZE + 2*MARGIN
#define BZ2     83              // BZM // 2
#define GX      84              // BZM//2 + 1
#define GZSTRIDE (BZM * GX)     // 14028
#define GRID_ELEMS (BZM * BZM * GX)  // 2,342,844
#define MR2     6400

__device__ int g_is64;   // 1 if grid3d_index is int64 on device, else 0

__global__ void detect_kernel(const int* __restrict__ g)
{
    const int r = 83 * GZSTRIDE + 83 * GX;   // interior element, even int32 offset
    g_is64 = (g[r + 1] == 0) ? 1 : 0;
}

__global__ __launch_bounds__(256) void svr_kernel(
    const float*  __restrict__ input,    // (256, 8)
    const float4* __restrict__ weight,   // (Nw, 8, 2) -> Nw*4 float4
    const float2* __restrict__ bias,     // (Nw, 2)
    const int*    __restrict__ grid3d,   // (167,167,84) int32 (or int64 LE)
    const float*  __restrict__ rot,      // (256, 3, 3)
    float2*       __restrict__ out)      // (256, 13041, 2)
{
    const int b    = blockIdx.y;
    const int p    = blockIdx.x * 256 + threadIdx.x;
    const int lane = threadIdx.x & 31;
    const unsigned FULL = 0xffffffffu;

    // ---- Per-point setup: 8 corner indices + trilinear weights -------------
    int   jc[8];
    float wt[8];
    float simag = 1.f;

    bool active = false;
    if (p < PTS) {
        const int xi2 = p % PX;           // 0..80
        const int iy  = p / PX - HW;      // -80..80
        if (xi2 * xi2 + iy * iy <= MR2) {
            active = true;
            const float* R = rot + b * 9;
            const float x = (float)xi2, y = (float)iy;
            float cx = R[0] * x + R[1] * y;
            float cy = R[3] * x + R[4] * y;
            float cz = R[6] * x + R[7] * y;
            if (cx < 0.f) { cx = -cx; cy = -cy; cz = -cz; simag = -1.f; }

            const float fx = floorf(cx), fy = floorf(cy), fz = floorf(cz);
            const int   ix = (int)fx,    iyc = (int)fy,   iz = (int)fz;
            const float tx = cx - fx,    ty = cy - fy,    tz = cz - fz;

            const float wxl[2] = {1.f - tx, tx};
            const float wyl[2] = {1.f - ty, ty};
            const float wzl[2] = {1.f - tz, tz};

            const int is64 = g_is64;
            #pragma unroll
            for (int dz = 0; dz < 2; ++dz) {
                const int zbase = (iz + dz + BZ2) * GZSTRIDE;
                #pragma unroll
                for (int dy = 0; dy < 2; ++dy) {
                    const int ybase = zbase + (iyc + dy + BZ2) * GX + ix;
                    #pragma unroll
                    for (int dx = 0; dx < 2; ++dx) {
                        const int c = dz * 4 + dy * 2 + dx;
                        const int lin = ybase + dx;
                        jc[c] = __ldg(grid3d + (is64 ? 2 * lin : lin));
                        wt[c] = wzl[dz] * wyl[dy] * wxl[dx];
                    }
                }
            }
        }
    }
    if (!active) {
        #pragma unroll
        for (int c = 0; c < 8; ++c) { jc[c] = -1; wt[c] = 0.f; }
    }

    // ---- Warp-cooperative gather + distributed dot -------------------------
    // Lane role: slot = lane&3 covers feature dims {2*slot, 2*slot+1} of a row.
    // For sub=0..3, lanes 4g..4g+3 load the full 64B row of point sub*8+g.
    const float* inb = input + b * ISIZE;      // uniform per block
    const int   slot = lane & 3;
    const float f0 = inb[2 * slot];
    const float f1 = inb[2 * slot + 1];
    const int   gsrc = lane >> 2;              // 0..7

    float br = 0.f, bi = 0.f;                  // owner-side bias accumulation
    float accr[4] = {0.f, 0.f, 0.f, 0.f};
    float acci[4] = {0.f, 0.f, 0.f, 0.f};

    #pragma unroll
    for (int c = 0; c < 8; ++c) {
        const int jo = jc[c];
        if (jo >= 0) {
            const float2 bb = __ldg(bias + jo);
            br += wt[c] * bb.x;
            bi += wt[c] * bb.y;
        }
        #pragma unroll
        for (int sub = 0; sub < 4; ++sub) {
            const int   src = sub * 8 + gsrc;
            const int   jr  = __shfl_sync(FULL, jo,    src);
            const float wr  = __shfl_sync(FULL, wt[c], src);
            if (jr >= 0) {
                const float4 w = __ldg(weight + (size_t)jr * 4 + slot);
                accr[sub] += wr * (f0 * w.x + f1 * w.z);
                acci[sub] += wr * (f0 * w.y + f1 * w.w);
            }
        }
    }

    // Reduce each sub over its 4-lane group (xor 1,2 stays within the group).
    #pragma unroll
    for (int sub = 0; sub < 4; ++sub) {
        accr[sub] += __shfl_xor_sync(FULL, accr[sub], 1);
        acci[sub] += __shfl_xor_sync(FULL, acci[sub], 1);
        accr[sub] += __shfl_xor_sync(FULL, accr[sub], 2);
        acci[sub] += __shfl_xor_sync(FULL, acci[sub], 2);
    }

    // Route each point's value back to its owner lane:
    // owner L's value lives in accr[L>>3] of lanes 4*(L&7)..4*(L&7)+3.
    const int from  = 4 * (lane & 7);
    const int mysub = lane >> 3;
    float vr = 0.f, vi = 0.f;
    #pragma unroll
    for (int s2 = 0; s2 < 4; ++s2) {
        const float tr = __shfl_sync(FULL, accr[s2], from);
        const float ti = __shfl_sync(FULL, acci[s2], from);
        if (mysub == s2) { vr = tr; vi = ti; }
    }
    vr += br;
    vi += bi;

    if (p < PTS) {
        out[(size_t)b * PTS + p] = make_float2(vr, vi * simag);
    }
}

extern "C" void kernel_launch(void* const* d_in, const int* in_sizes, int n_in,
                              void* d_out, int out_size)
{
    // Identify inputs by element count — robust to metadata ordering.
    const void* p_input  = nullptr;  // 2048
    const void* p_rot    = nullptr;  // 2304
    const void* p_grid   = nullptr;  // 2,342,844
    const void* p_weight = nullptr;  // Nw*16 (larger of remaining pair)
    const void* p_bias   = nullptr;  // Nw*2
    long long wcand[2] = {0, 0};
    const void* pcand[2] = {nullptr, nullptr};
    int ncand = 0;

    for (int i = 0; i < n_in; ++i) {
        const long long s = in_sizes[i];
        if      (s == BATCH * ISIZE)           p_input = d_in[i];
        else if (s == BATCH * 9)               p_rot   = d_in[i];
        else if (s == (long long)GRID_ELEMS)   p_grid  = d_in[i];
        else if (s == PTS * 2 || s == 1)       { /* grid2d_coord / max_r unused */ }
        else if (ncand < 2)                    { wcand[ncand] = s; pcand[ncand] = d_in[i]; ++ncand; }
    }
    if (ncand == 2) {
        if (wcand[0] > wcand[1]) { p_weight = pcand[0]; p_bias = pcand[1]; }
        else                     { p_weight = pcand[1]; p_bias = pcand[0]; }
    }

    detect_kernel<<<1, 1>>>((const int*)p_grid);

    dim3 grid((PTS + 255) / 256, BATCH);
    svr_kernel<<<grid, 256>>>((const float*)p_input,
                              (const float4*)p_weight,
                              (const float2*)p_bias,
                              (const int*)p_grid,
                              (const float*)p_rot,
                              (float2*)d_out);
}